// round 5
// baseline (speedup 1.0000x reference)
#include <cuda_runtime.h>

#define N_STATE 131072
#define H 128
#define SEG 64          // n-segments in kernel A
#define RPB 4           // rows per block in kernel A
#define JSPLIT 4        // i-splits in kernel C
#define JROWS (H / JSPLIT)

// Scratch (device globals — no allocation allowed)
__device__ float g_xnorm[N_STATE];
__device__ float g_scale[N_STATE];
__device__ float g_ypart[SEG * H];
__device__ float g_r[H];
__device__ float g_jvpart[JSPLIT * N_STATE];

// ---------------------------------------------------------------------------
// Kernel N: x_norm[n] = (2 s - mx - mn) / (mx - mn);  scale[n] = 2/(mx - mn)
// ---------------------------------------------------------------------------
__global__ __launch_bounds__(256)
void k_norm(const float* __restrict__ state,
            const float* __restrict__ xmax,
            const float* __restrict__ xmin)
{
    const int i = blockIdx.x * blockDim.x + threadIdx.x;   // float4 index
    float4 s  = ((const float4*)state)[i];
    float4 mx = ((const float4*)xmax)[i];
    float4 mn = ((const float4*)xmin)[i];
    float4 inv, xn, sc;
    inv.x = 1.0f / (mx.x - mn.x);
    inv.y = 1.0f / (mx.y - mn.y);
    inv.z = 1.0f / (mx.z - mn.z);
    inv.w = 1.0f / (mx.w - mn.w);
    xn.x = (2.0f * s.x - mx.x - mn.x) * inv.x;
    xn.y = (2.0f * s.y - mx.y - mn.y) * inv.y;
    xn.z = (2.0f * s.z - mx.z - mn.z) * inv.z;
    xn.w = (2.0f * s.w - mx.w - mn.w) * inv.w;
    sc.x = 2.0f * inv.x;  sc.y = 2.0f * inv.y;
    sc.z = 2.0f * inv.z;  sc.w = 2.0f * inv.w;
    ((float4*)g_xnorm)[i] = xn;
    ((float4*)g_scale)[i] = sc;
}

// ---------------------------------------------------------------------------
// Kernel A: partial y. blockIdx.x = segment, blockIdx.y = rowgroup (RPB rows).
// grid (64, 32) = 2048 blocks x 256 threads. 4 W0 streams/thread — no spills.
// ---------------------------------------------------------------------------
__global__ __launch_bounds__(256)
void k_fwd_matvec(const float* __restrict__ W0)
{
    const int seg = blockIdx.x;
    const int row0 = blockIdx.y * RPB;
    const int chunk4 = (N_STATE / SEG) / 4;                // 512 float4s

    const float4* __restrict__ xn = (const float4*)g_xnorm + (size_t)seg * chunk4;
    const float4* __restrict__ w0 = (const float4*)(W0 + (size_t)row0 * N_STATE) + (size_t)seg * chunk4;
    const size_t rstride4 = N_STATE / 4;

    float acc[RPB];
    #pragma unroll
    for (int r = 0; r < RPB; r++) acc[r] = 0.0f;

    #pragma unroll
    for (int it = 0; it < (N_STATE / SEG) / 4 / 256; it++) {
        const int i = it * 256 + threadIdx.x;
        float4 x = xn[i];
        #pragma unroll
        for (int r = 0; r < RPB; r++) {
            float4 wv = w0[(size_t)r * rstride4 + i];
            acc[r] += wv.x * x.x + wv.y * x.y + wv.z * x.z + wv.w * x.w;
        }
    }

    __shared__ float red[8][RPB];
    const int lane = threadIdx.x & 31, warp = threadIdx.x >> 5;
    #pragma unroll
    for (int r = 0; r < RPB; r++) {
        float v = acc[r];
        #pragma unroll
        for (int o = 16; o > 0; o >>= 1)
            v += __shfl_down_sync(0xffffffffu, v, o);
        if (lane == 0) red[warp][r] = v;
    }
    __syncthreads();
    if (threadIdx.x < RPB) {
        float v = 0.0f;
        #pragma unroll
        for (int w = 0; w < 8; w++) v += red[w][threadIdx.x];
        g_ypart[seg * H + row0 + threadIdx.x] = v;
    }
}

// ---------------------------------------------------------------------------
// Kernel B: sum partials -> y, forward tanh chain, backward collapse -> g_r.
// ---------------------------------------------------------------------------
__global__ __launch_bounds__(128, 1)
void k_core(const float* __restrict__ b0,
            const float* __restrict__ W1, const float* __restrict__ b1,
            const float* __restrict__ W2, const float* __restrict__ b2,
            const float* __restrict__ W3, const float* __restrict__ b3,
            const float* __restrict__ Wout, const float* __restrict__ bout,
            float* __restrict__ out)
{
    __shared__ float v[H];
    __shared__ float t[H];
    __shared__ float d0[H], d1[H], d2[H];
    __shared__ float red[4];

    const int j = threadIdx.x;

    float y = 0.0f;
    #pragma unroll
    for (int s = 0; s < SEG; s++) y += g_ypart[s * H + j];

    float V0 = tanhf(y + b0[j]);
    d0[j] = 1.0f - V0 * V0;
    v[j] = V0;
    __syncthreads();

    float acc = b1[j];
    #pragma unroll 8
    for (int k = 0; k < H; k++) acc += W1[j * H + k] * v[k];
    float V1 = tanhf(acc);
    d1[j] = 1.0f - V1 * V1;
    __syncthreads();
    v[j] = V1;
    __syncthreads();

    acc = b2[j];
    #pragma unroll 8
    for (int k = 0; k < H; k++) acc += W2[j * H + k] * v[k];
    float V2 = tanhf(acc);
    d2[j] = 1.0f - V2 * V2;
    __syncthreads();
    v[j] = V2;
    __syncthreads();

    acc = b3[j];
    #pragma unroll 8
    for (int k = 0; k < H; k++) acc += W3[j * H + k] * v[k];
    __syncthreads();
    v[j] = acc;
    __syncthreads();

    float p = Wout[j] * v[j];
    #pragma unroll
    for (int o = 16; o > 0; o >>= 1)
        p += __shfl_down_sync(0xffffffffu, p, o);
    if ((j & 31) == 0) red[j >> 5] = p;
    __syncthreads();
    if (j == 0)
        out[0] = red[0] + red[1] + red[2] + red[3] + bout[0];

    // backward: r^T = Wout W3 D2 W2 D1 W1 D0
    t[j] = Wout[j];
    __syncthreads();

    acc = 0.0f;
    #pragma unroll 8
    for (int i = 0; i < H; i++) acc += t[i] * W3[i * H + j];
    acc *= d2[j];
    __syncthreads();
    t[j] = acc;
    __syncthreads();

    acc = 0.0f;
    #pragma unroll 8
    for (int i = 0; i < H; i++) acc += t[i] * W2[i * H + j];
    acc *= d1[j];
    __syncthreads();
    t[j] = acc;
    __syncthreads();

    acc = 0.0f;
    #pragma unroll 8
    for (int i = 0; i < H; i++) acc += t[i] * W1[i * H + j];
    acc *= d0[j];
    g_r[j] = acc;
}

// ---------------------------------------------------------------------------
// Kernel C: partial JV. blockIdx.x = n-chunk (float2), blockIdx.y = i-split.
// grid (256, 4) = 1024 blocks x 256 threads -> ~86% occupancy, float2 loads.
// ---------------------------------------------------------------------------
__global__ __launch_bounds__(256)
void k_jv_part(const float* __restrict__ W0)
{
    __shared__ float r[JROWS];
    const int i0 = blockIdx.y * JROWS;
    if (threadIdx.x < JROWS) r[threadIdx.x] = g_r[i0 + threadIdx.x];
    __syncthreads();

    const int n2 = blockIdx.x * blockDim.x + threadIdx.x;   // float2 index
    const float2* __restrict__ w = (const float2*)W0 + (size_t)i0 * (N_STATE / 2);
    const size_t stride2 = N_STATE / 2;

    float ax = 0.0f, ay = 0.0f;
    #pragma unroll 8
    for (int i = 0; i < JROWS; i++) {
        float2 wv = w[(size_t)i * stride2 + n2];
        float ri = r[i];
        ax += ri * wv.x;
        ay += ri * wv.y;
    }

    ((float2*)g_jvpart)[(size_t)blockIdx.y * (N_STATE / 2) + n2] = make_float2(ax, ay);
}

// ---------------------------------------------------------------------------
// Kernel D: combine partials, apply scale, write out[1..N].
// ---------------------------------------------------------------------------
__global__ __launch_bounds__(256)
void k_combine(float* __restrict__ out)
{
    const int i4 = blockIdx.x * blockDim.x + threadIdx.x;   // float4 index
    float4 a = ((const float4*)g_jvpart)[i4];
    float4 b = ((const float4*)(g_jvpart + N_STATE))[i4];
    float4 c = ((const float4*)(g_jvpart + 2 * N_STATE))[i4];
    float4 d = ((const float4*)(g_jvpart + 3 * N_STATE))[i4];
    float4 sc = ((const float4*)g_scale)[i4];
    const int n = i4 * 4;
    out[1 + n + 0] = (a.x + b.x + c.x + d.x) * sc.x;
    out[1 + n + 1] = (a.y + b.y + c.y + d.y) * sc.y;
    out[1 + n + 2] = (a.z + b.z + c.z + d.z) * sc.z;
    out[1 + n + 3] = (a.w + b.w + c.w + d.w) * sc.w;
}

// ---------------------------------------------------------------------------
extern "C" void kernel_launch(void* const* d_in, const int* in_sizes, int n_in,
                              void* d_out, int out_size)
{
    const float* state = (const float*)d_in[0];
    const float* xmax  = (const float*)d_in[1];
    const float* xmin  = (const float*)d_in[2];
    const float* W0    = (const float*)d_in[3];
    const float* b0    = (const float*)d_in[4];
    const float* W1    = (const float*)d_in[5];
    const float* b1    = (const float*)d_in[6];
    const float* W2    = (const float*)d_in[7];
    const float* b2    = (const float*)d_in[8];
    const float* W3    = (const float*)d_in[9];
    const float* b3    = (const float*)d_in[10];
    const float* Wout  = (const float*)d_in[11];
    const float* bout  = (const float*)d_in[12];
    float* out = (float*)d_out;

    k_norm<<<N_STATE / 4 / 256, 256>>>(state, xmax, xmin);
    dim3 gridA(SEG, H / RPB);
    k_fwd_matvec<<<gridA, 256>>>(W0);
    k_core<<<1, H>>>(b0, W1, b1, W2, b2, W3, b3, Wout, bout, out);
    dim3 gridC(N_STATE / 2 / 256, JSPLIT);
    k_jv_part<<<gridC, 256>>>(W0);
    k_combine<<<N_STATE / 4 / 256, 256>>>(out);
}